// round 17
// baseline (speedup 1.0000x reference)
#include <cuda_runtime.h>

#define L_DIM 512
#define B_DIM 64
#define H_DIM 1024
#define K2_GRID 296   // 2 blocks per SM on 148 SMs
#define NB1 64        // K1 grid size (all resident: 64 <= 148 SMs)

// Scratch (no allocations allowed). Zero-initialized at module load.
__device__ __align__(16) float g_scratch[NB1 * H_DIM];  // per-block partials [j][h]
__device__ __align__(16) float g_u[H_DIM];              // final u
__device__ float g_attn[B_DIM * L_DIM];
__device__ int g_cnt1;                                   // arrive counter (self-resetting)
__device__ int g_rel1;                                   // monotonic release generation

// ---------------------------------------------------------------------------
// K1: u[h] = sum_k We[k,h] * v[k], two phases with an in-kernel grid sync.
// Phase A: 64 blocks x 1024 thr; block owns 16 consecutive k-rows and reads
//   each row's We half as ONE contiguous 4KB chunk (threads 0-255 cover it,
//   4 rows per round, 4 rounds -> MLP=4/thread, 64KB in flight per SM).
//   16KB smem reduce -> one 1024-wide partial per block (g_scratch, L2).
// Grid sync: generation-counter barrier (monotonic g_rel1 -> replay-safe;
//   counter self-resets; all 64 blocks resident -> no deadlock; no data
//   atomics -> deterministic).
// Phase B: block b k-reduces the 64 partials for h in [16b,16b+16) -> g_u.
// ---------------------------------------------------------------------------
__global__ void __launch_bounds__(1024) compute_u_kernel(const float* __restrict__ W_att,
                                                         const float* __restrict__ vec) {
    __shared__ float  sv[16];
    __shared__ float4 red[4][256];            // 16 KB
    __shared__ float  r2[1024];               // 4 KB (phase B)
    const int t  = threadIdx.x;
    const int b  = blockIdx.x;
    const int ro = t >> 8;                    // row offset within round, 0..3
    const int c4 = t & 255;                   // h-quad (h = 4*c4)
    const int k0 = b * 16;

    if (t < 16) sv[t] = vec[k0 + t];
    __syncthreads();

    float4 acc = make_float4(0.f, 0.f, 0.f, 0.f);
    #pragma unroll
    for (int r = 0; r < 4; r++) {
        const int k = k0 + r * 4 + ro;
        const float4 w = *reinterpret_cast<const float4*>(
            &W_att[(size_t)k * (2 * H_DIM) + H_DIM + c4 * 4]);
        const float vk = sv[r * 4 + ro];
        acc.x += w.x * vk;
        acc.y += w.y * vk;
        acc.z += w.z * vk;
        acc.w += w.w * vk;
    }
    red[ro][c4] = acc;
    __syncthreads();

    if (t < 256) {
        float4 a = red[0][t];
        const float4 p1 = red[1][t], p2 = red[2][t], p3 = red[3][t];
        a.x += p1.x + p2.x + p3.x;
        a.y += p1.y + p2.y + p3.y;
        a.z += p1.z + p2.z + p3.z;
        a.w += p1.w + p2.w + p3.w;
        reinterpret_cast<float4*>(&g_scratch[b * H_DIM])[t] = a;
    }

    // ---- grid sync (release writes, arrive, spin on generation) ----
    __threadfence();
    __syncthreads();
    if (t == 0) {
        const int r0 = *(volatile int*)&g_rel1;     // read BEFORE my arrival
        const int old = atomicAdd(&g_cnt1, 1);
        if (old == NB1 - 1) {
            g_cnt1 = 0;                              // safe: nobody spins on cnt
            __threadfence();
            atomicAdd(&g_rel1, 1);                   // release this generation
        } else {
            while (*(volatile int*)&g_rel1 == r0) __nanosleep(40);
        }
        __threadfence();
    }
    __syncthreads();

    // ---- phase B: k-reduce 64 partials for h in [16b, 16b+16) ----
    {
        const int hl = t & 15;                       // h within block's range
        const int j  = t >> 4;                       // partial index 0..63
        r2[j * 16 + hl] = __ldcg(&g_scratch[j * H_DIM + b * 16 + hl]);
        __syncthreads();
        if (t < 16) {
            float s = 0.f;
            #pragma unroll
            for (int jj = 0; jj < 64; jj++) s += r2[jj * 16 + t];
            g_u[b * 16 + t] = s;
        }
    }
}

// ---------------------------------------------------------------------------
// K2: attn[b,l] = <hs_encoder[l,b,:], u>   (the 134 MB streaming kernel)
// PERSISTENT: 296 blocks x 512 thr; staging is ONE float4/thread from the
// finalized g_u. Each warp grid-strides over rows (~7 per warp). Hot loop:
// __ldcs float4 (evict-first), MLP=8. NO fences, NO atomics.
// ---------------------------------------------------------------------------
__global__ void __launch_bounds__(512) dot_kernel(const float* __restrict__ hs) {
    __shared__ float4 su[H_DIM / 4];          // 4 KB
    const int t = threadIdx.x;
    if (t < H_DIM / 4)
        su[t] = __ldcg(reinterpret_cast<const float4*>(g_u) + t);
    __syncthreads();

    const int warp  = t >> 5;
    const int lane  = t & 31;
    const int nwarp = K2_GRID * 16;           // total warps in grid

    for (int row = blockIdx.x * 16 + warp; row < L_DIM * B_DIM; row += nwarp) {
        const float4* rp = reinterpret_cast<const float4*>(hs) + (size_t)row * (H_DIM / 4);

        float acc = 0.f;
        #pragma unroll
        for (int j = 0; j < 8; j++) {
            const int idx = lane + j * 32;
            const float4 x = __ldcs(rp + idx);    // streaming, evict-first
            const float4 u = su[idx];
            acc += x.x * u.x + x.y * u.y + x.z * u.z + x.w * u.w;
        }
        #pragma unroll
        for (int o = 16; o; o >>= 1)
            acc += __shfl_xor_sync(0xffffffffu, acc, o);

        if (lane == 0) {
            const int l = row >> 6;               // row / B
            const int b = row & 63;               // row % B
            g_attn[b * L_DIM + l] = acc;
        }
    }
}

// ---------------------------------------------------------------------------
// K3: out[b, 0, l] = softmax_l(attn[b, l]).  One block per batch, 512 threads.
// ---------------------------------------------------------------------------
__global__ void __launch_bounds__(512) softmax_kernel(float* __restrict__ out) {
    __shared__ float sm[16];
    const int b = blockIdx.x;
    const int t = threadIdx.x;                // 0..511
    const int lane = t & 31, w = t >> 5;

    const float a = g_attn[b * L_DIM + t];

    float m = a;
    #pragma unroll
    for (int o = 16; o; o >>= 1) m = fmaxf(m, __shfl_xor_sync(0xffffffffu, m, o));
    if (lane == 0) sm[w] = m;
    __syncthreads();
    float M = sm[0];
    #pragma unroll
    for (int i = 1; i < 16; i++) M = fmaxf(M, sm[i]);
    __syncthreads();

    const float e = expf(a - M);

    float s = e;
    #pragma unroll
    for (int o = 16; o; o >>= 1) s += __shfl_xor_sync(0xffffffffu, s, o);
    if (lane == 0) sm[w] = s;
    __syncthreads();
    float S = sm[0];
    #pragma unroll
    for (int i = 1; i < 16; i++) S += sm[i];

    out[b * L_DIM + t] = e / S;
}

// ---------------------------------------------------------------------------
// Inputs (metadata order): hidden, hs_encoder, W_att, b_att, vector
// hidden / b_att / Wh are mathematically dead (softmax shift invariance).
// ---------------------------------------------------------------------------
extern "C" void kernel_launch(void* const* d_in, const int* in_sizes, int n_in,
                              void* d_out, int out_size) {
    const float* hs  = (const float*)d_in[1];   // (512, 64, 1024)
    const float* W   = (const float*)d_in[2];   // (1024, 2048)
    const float* vec = (const float*)d_in[4];   // (1024, 1)
    float* out = (float*)d_out;                 // (64, 1, 512)

    compute_u_kernel<<<NB1, 1024>>>(W, vec);
    dot_kernel<<<K2_GRID, 512>>>(hs);
    softmax_kernel<<<B_DIM, 512>>>(out);
}